// round 6
// baseline (speedup 1.0000x reference)
#include <cuda_runtime.h>
#include <math.h>
#include <stdint.h>

// ---------------- problem constants ----------------
#define CB   128     // batch
#define CN   49      // spatial tokens
#define CIN  2048    // backbone channels
#define CG   256     // query groups
#define CD   768     // decoder dim
#define CH   8       // heads
#define CHD  96      // head dim
#define CFF  2048    // ffn dim
#define NCLS 12547
#define CDUP 50

// ---------------- scratch (device globals; no allocation allowed) ----------------
__device__ float g_mem  [CB*CN*CD];
__device__ float g_k    [CB*CN*CD];
__device__ float g_v    [CB*CN*CD];
__device__ float g_tln  [CG*CD];
__device__ float g_q    [CG*CD];
__device__ float g_attn [CB*CG*CD];
__device__ float g_oproj[CB*CG*CD];
__device__ float g_t2   [CB*CG*CD];
__device__ float g_ff1  [CB*CG*CFF];
__device__ float g_ff2  [CB*CG*CD];
__device__ float g_h    [CB*CG*CD];

// ============================================================================
// TF32 tensor-core GEMM: C[M,N] = A[M,K] @ B[K,N] + bias[N]  (optional ReLU)
// Requires M%128==0, N%128==0, K%16==0 (true for all calls here).
// 128x128x16 block tile, 256 threads (8 warps, 4x2), warp tile 32x64,
// mma.sync.m16n8k8.tf32, DOUBLE-BUFFERED smem mainloop (one barrier/iter),
// register-staged gmem prefetch 2 tiles ahead, rna-rounded tf32 inputs.
// ============================================================================
#define BM 128
#define BN 128
#define BK 16
#define ASTRIDE (BK + 4)     // 20 floats  -> conflict-free A-frag LDS
#define BSTRIDE (BN + 8)     // 136 floats -> conflict-free B-frag LDS
#define ASZ (BM * ASTRIDE)   // 2560
#define BSZ (BK * BSTRIDE)   // 2176

__device__ __forceinline__ float to_tf32(float x) {
    asm("cvt.rna.tf32.f32 %0, %0;" : "+f"(x));
    return x;
}

__device__ __forceinline__ void mma1688(float* d, const uint32_t* a, const uint32_t* b) {
    asm volatile(
        "mma.sync.aligned.m16n8k8.row.col.f32.tf32.tf32.f32 "
        "{%0,%1,%2,%3}, {%4,%5,%6,%7}, {%8,%9}, {%0,%1,%2,%3};"
        : "+f"(d[0]), "+f"(d[1]), "+f"(d[2]), "+f"(d[3])
        : "r"(a[0]), "r"(a[1]), "r"(a[2]), "r"(a[3]), "r"(b[0]), "r"(b[1]));
}

template<bool RELU>
__global__ __launch_bounds__(256, 2) void gemm_tf32_kernel(
    const float* __restrict__ A, const float* __restrict__ B,
    const float* __restrict__ bias, float* __restrict__ C,
    int M, int N, int K)
{
    __shared__ float As[2][ASZ];
    __shared__ float Bs[2][BSZ];

    const int tid  = threadIdx.x;
    const int lane = tid & 31;
    const int warp = tid >> 5;
    const int wm   = warp & 3;        // 4 warps along M
    const int wn   = warp >> 2;       // 2 warps along N
    const int m0   = blockIdx.y * BM;
    const int n0   = blockIdx.x * BN;

    const int g = lane >> 2;          // 0..7
    const int t = lane & 3;           // 0..3

    // gmem staging: 2 float4 each for A and B tiles per thread
    const int i0 = tid, i1 = tid + 256;
    const int ar0 = i0 >> 2,  ac0 = (i0 & 3) * 4;
    const int ar1 = i1 >> 2,  ac1 = (i1 & 3) * 4;
    const int br0 = i0 >> 5,  bc0 = (i0 & 31) * 4;
    const int br1 = i1 >> 5,  bc1 = (i1 & 31) * 4;

    const float* Ap0 = A + (size_t)(m0 + ar0) * K + ac0;
    const float* Ap1 = A + (size_t)(m0 + ar1) * K + ac1;
    const float* Bp0 = B + (size_t)br0 * N + n0 + bc0;
    const float* Bp1 = B + (size_t)br1 * N + n0 + bc1;

    float acc[2][8][4];
    #pragma unroll
    for (int im = 0; im < 2; im++)
        #pragma unroll
        for (int in = 0; in < 8; in++)
            #pragma unroll
            for (int r = 0; r < 4; r++) acc[im][in][r] = 0.f;

    const int warp_m = wm * 32;
    const int warp_n = wn * 64;
    const int nT = K / BK;

    // ---- prologue: tile 0 -> regs -> smem[0]; prefetch tile 1 into regs ----
    float4 ra0 = *(const float4*)Ap0;
    float4 ra1 = *(const float4*)Ap1;
    float4 rb0 = *(const float4*)Bp0;
    float4 rb1 = *(const float4*)Bp1;
    {
        float4 v;
        v.x = to_tf32(ra0.x); v.y = to_tf32(ra0.y); v.z = to_tf32(ra0.z); v.w = to_tf32(ra0.w);
        *(float4*)&As[0][ar0 * ASTRIDE + ac0] = v;
        v.x = to_tf32(ra1.x); v.y = to_tf32(ra1.y); v.z = to_tf32(ra1.z); v.w = to_tf32(ra1.w);
        *(float4*)&As[0][ar1 * ASTRIDE + ac1] = v;
        v.x = to_tf32(rb0.x); v.y = to_tf32(rb0.y); v.z = to_tf32(rb0.z); v.w = to_tf32(rb0.w);
        *(float4*)&Bs[0][br0 * BSTRIDE + bc0] = v;
        v.x = to_tf32(rb1.x); v.y = to_tf32(rb1.y); v.z = to_tf32(rb1.z); v.w = to_tf32(rb1.w);
        *(float4*)&Bs[0][br1 * BSTRIDE + bc1] = v;
    }
    if (nT > 1) {
        ra0 = *(const float4*)(Ap0 + BK);
        ra1 = *(const float4*)(Ap1 + BK);
        rb0 = *(const float4*)(Bp0 + (size_t)BK * N);
        rb1 = *(const float4*)(Bp1 + (size_t)BK * N);
    }
    __syncthreads();

    // ---- mainloop: one barrier per iter; STS/LDG overlap mma ----
    for (int it = 0; it < nT; ++it) {
        const int cur = it & 1;

        if (it + 1 < nT) {           // store prefetched tile (it+1) into other buffer
            float* as = As[cur ^ 1];
            float* bs = Bs[cur ^ 1];
            float4 v;
            v.x = to_tf32(ra0.x); v.y = to_tf32(ra0.y); v.z = to_tf32(ra0.z); v.w = to_tf32(ra0.w);
            *(float4*)&as[ar0 * ASTRIDE + ac0] = v;
            v.x = to_tf32(ra1.x); v.y = to_tf32(ra1.y); v.z = to_tf32(ra1.z); v.w = to_tf32(ra1.w);
            *(float4*)&as[ar1 * ASTRIDE + ac1] = v;
            v.x = to_tf32(rb0.x); v.y = to_tf32(rb0.y); v.z = to_tf32(rb0.z); v.w = to_tf32(rb0.w);
            *(float4*)&bs[br0 * BSTRIDE + bc0] = v;
            v.x = to_tf32(rb1.x); v.y = to_tf32(rb1.y); v.z = to_tf32(rb1.z); v.w = to_tf32(rb1.w);
            *(float4*)&bs[br1 * BSTRIDE + bc1] = v;
        }
        if (it + 2 < nT) {           // prefetch tile (it+2) into regs
            const int kp = (it + 2) * BK;
            ra0 = *(const float4*)(Ap0 + kp);
            ra1 = *(const float4*)(Ap1 + kp);
            rb0 = *(const float4*)(Bp0 + (size_t)kp * N);
            rb1 = *(const float4*)(Bp1 + (size_t)kp * N);
        }

        const float* as = As[cur];
        const float* bs = Bs[cur];
        #pragma unroll
        for (int kk = 0; kk < BK; kk += 8) {
            uint32_t af[2][4];
            #pragma unroll
            for (int im = 0; im < 2; im++) {
                const int r = warp_m + im * 16 + g;
                af[im][0] = __float_as_uint(as[(r    ) * ASTRIDE + kk + t    ]);
                af[im][1] = __float_as_uint(as[(r + 8) * ASTRIDE + kk + t    ]);
                af[im][2] = __float_as_uint(as[(r    ) * ASTRIDE + kk + t + 4]);
                af[im][3] = __float_as_uint(as[(r + 8) * ASTRIDE + kk + t + 4]);
            }
            uint32_t bf[8][2];
            #pragma unroll
            for (int in = 0; in < 8; in++) {
                const int c = warp_n + in * 8 + g;
                bf[in][0] = __float_as_uint(bs[(kk + t    ) * BSTRIDE + c]);
                bf[in][1] = __float_as_uint(bs[(kk + t + 4) * BSTRIDE + c]);
            }
            #pragma unroll
            for (int im = 0; im < 2; im++)
                #pragma unroll
                for (int in = 0; in < 8; in++)
                    mma1688(acc[im][in], af[im], bf[in]);
        }
        __syncthreads();
    }

    // epilogue: bias (+ReLU), direct to gmem
    #pragma unroll
    for (int in = 0; in < 8; in++) {
        const int c0 = n0 + warp_n + in * 8 + t * 2;
        float2 bv = *(const float2*)(bias + c0);
        #pragma unroll
        for (int im = 0; im < 2; im++) {
            const int r0 = m0 + warp_m + im * 16 + g;
            float2 o0, o1;
            o0.x = acc[im][in][0] + bv.x;
            o0.y = acc[im][in][1] + bv.y;
            o1.x = acc[im][in][2] + bv.x;
            o1.y = acc[im][in][3] + bv.y;
            if (RELU) {
                o0.x = fmaxf(o0.x, 0.f); o0.y = fmaxf(o0.y, 0.f);
                o1.x = fmaxf(o1.x, 0.f); o1.y = fmaxf(o1.y, 0.f);
            }
            *(float2*)(C + (size_t)r0 * N + c0)       = o0;
            *(float2*)(C + (size_t)(r0 + 8) * N + c0) = o1;
        }
    }
}

// ============================================================================
// LayerNorm over D=768 with fused residual: out[row] = LN(a[row] + res[row % rowmod])
// ============================================================================
__global__ __launch_bounds__(256) void ln_residual_kernel(
    const float* __restrict__ a, const float* __restrict__ res,
    const float* __restrict__ gamma, const float* __restrict__ beta,
    float* __restrict__ out, int rowmod)
{
    __shared__ float sh[8];
    __shared__ float s_mean, s_rstd;

    const int row = blockIdx.x;
    const int tid = threadIdx.x;
    const float* ar = a   + (size_t)row * CD;
    const float* rr = res + (size_t)(row % rowmod) * CD;

    float x[3];
    #pragma unroll
    for (int i = 0; i < 3; i++) {
        int j = tid + i * 256;
        x[i] = ar[j] + rr[j];
    }

    float s = x[0] + x[1] + x[2];
    #pragma unroll
    for (int o = 16; o > 0; o >>= 1) s += __shfl_down_sync(0xffffffffu, s, o);
    if ((tid & 31) == 0) sh[tid >> 5] = s;
    __syncthreads();
    if (tid < 32) {
        float v = (tid < 8) ? sh[tid] : 0.f;
        #pragma unroll
        for (int o = 4; o > 0; o >>= 1) v += __shfl_down_sync(0xffffffffu, v, o);
        if (tid == 0) s_mean = v * (1.f / CD);
    }
    __syncthreads();
    const float m = s_mean;

    float d2 = 0.f;
    #pragma unroll
    for (int i = 0; i < 3; i++) { float d = x[i] - m; d2 += d * d; }
    #pragma unroll
    for (int o = 16; o > 0; o >>= 1) d2 += __shfl_down_sync(0xffffffffu, d2, o);
    if ((tid & 31) == 0) sh[tid >> 5] = d2;
    __syncthreads();
    if (tid < 32) {
        float v = (tid < 8) ? sh[tid] : 0.f;
        #pragma unroll
        for (int o = 4; o > 0; o >>= 1) v += __shfl_down_sync(0xffffffffu, v, o);
        if (tid == 0) s_rstd = rsqrtf(v * (1.f / CD) + 1e-5f);
    }
    __syncthreads();
    const float rs = s_rstd;

    float* orow = out + (size_t)row * CD;
    #pragma unroll
    for (int i = 0; i < 3; i++) {
        int j = tid + i * 256;
        orow[j] = (x[i] - m) * rs * gamma[j] + beta[j];
    }
}

// ============================================================================
// Cross-attention. q is batch-independent [G, D]. k,v: [B, N, D]. o: [B, G, D].
// ============================================================================
__global__ __launch_bounds__(256) void attn_kernel(
    const float* __restrict__ q, const float* __restrict__ k,
    const float* __restrict__ v, float* __restrict__ o)
{
    const int h = blockIdx.x;
    const int b = blockIdx.y;
    __shared__ float ks[CN][CHD];
    __shared__ float vs[CN][CHD];

    const int tid = threadIdx.x;
    for (int i = tid; i < CN * CHD; i += 256) {
        int n = i / CHD, d = i % CHD;
        size_t gi = (size_t)(b * CN + n) * CD + h * CHD + d;
        ks[n][d] = k[gi];
        vs[n][d] = v[gi];
    }
    __syncthreads();

    const int g = tid;
    float p[CN];
    #pragma unroll
    for (int n = 0; n < CN; n++) p[n] = 0.f;

    const float* qrow = q + (size_t)g * CD + h * CHD;
    for (int dc = 0; dc < CHD; dc += 8) {
        float q8[8];
        #pragma unroll
        for (int j = 0; j < 8; j++) q8[j] = qrow[dc + j];
        #pragma unroll
        for (int n = 0; n < CN; n++) {
            float s = 0.f;
            #pragma unroll
            for (int j = 0; j < 8; j++) s += q8[j] * ks[n][dc + j];
            p[n] += s;
        }
    }

    const float scale = rsqrtf((float)CHD);
    float mx = -1e30f;
    #pragma unroll
    for (int n = 0; n < CN; n++) { p[n] *= scale; mx = fmaxf(mx, p[n]); }
    float sum = 0.f;
    #pragma unroll
    for (int n = 0; n < CN; n++) { p[n] = expf(p[n] - mx); sum += p[n]; }
    const float inv = 1.f / sum;
    #pragma unroll
    for (int n = 0; n < CN; n++) p[n] *= inv;

    float* orow = o + (size_t)(b * CG + g) * CD + h * CHD;
    for (int d = 0; d < CHD; d++) {
        float acc = 0.f;
        #pragma unroll
        for (int n = 0; n < CN; n++) acc += p[n] * vs[n][d];
        orow[d] = acc;
    }
}

// ============================================================================
// GroupFC: logits[b, g*50+f] = h[b,g,:] . Wg[g,:,f] + bg
// 4-batch register blocking: each thread serves batches b0, b0+16, +32, +48,
// reusing every Wg load 4x (Wg L2 traffic cut 4x vs 1-batch version).
// grid (CG, CB/64), block 16*50=800: thread = (bi, f)
// ============================================================================
__global__ __launch_bounds__(800) void groupfc_kernel(
    const float* __restrict__ h, const float* __restrict__ Wg,
    const float* __restrict__ bg, float* __restrict__ out)
{
    const int g   = blockIdx.x;
    const int tid = threadIdx.x;
    const int f   = tid % CDUP;
    const int bi  = tid / CDUP;            // 0..15
    const int b0  = blockIdx.y * 64 + bi;  // + {0,16,32,48}

    const float* w  = Wg + (size_t)g * CD * CDUP + f;
    const float* h0 = h + ((size_t)(b0     ) * CG + g) * CD;
    const float* h1 = h + ((size_t)(b0 + 16) * CG + g) * CD;
    const float* h2 = h + ((size_t)(b0 + 32) * CG + g) * CD;
    const float* h3 = h + ((size_t)(b0 + 48) * CG + g) * CD;

    float a0 = 0.f, a1 = 0.f, a2 = 0.f, a3 = 0.f;
    #pragma unroll 4
    for (int d = 0; d < CD; d++) {
        float wv = w[(size_t)d * CDUP];
        a0 += h0[d] * wv;
        a1 += h1[d] * wv;
        a2 += h2[d] * wv;
        a3 += h3[d] * wv;
    }

    const int c = g * CDUP + f;
    if (c < NCLS) {
        const float bb = bg[c];
        out[(size_t)(b0     ) * NCLS + c] = a0 + bb;
        out[(size_t)(b0 + 16) * NCLS + c] = a1 + bb;
        out[(size_t)(b0 + 32) * NCLS + c] = a2 + bb;
        out[(size_t)(b0 + 48) * NCLS + c] = a3 + bb;
    }
}

// ============================================================================
// Orchestration
// ============================================================================
static inline float* sym(const void* s)
{
    void* p = nullptr;
    cudaGetSymbolAddress(&p, s);
    return (float*)p;
}

extern "C" void kernel_launch(void* const* d_in, const int* in_sizes, int n_in,
                              void* d_out, int out_size)
{
    const float* x       = (const float*)d_in[0];
    const float* W_embed = (const float*)d_in[1];
    const float* b_embed = (const float*)d_in[2];
    const float* query   = (const float*)d_in[3];
    const float* Wq = (const float*)d_in[4];  const float* bq = (const float*)d_in[5];
    const float* Wk = (const float*)d_in[6];  const float* bk = (const float*)d_in[7];
    const float* Wv = (const float*)d_in[8];  const float* bv = (const float*)d_in[9];
    const float* Wo = (const float*)d_in[10]; const float* bo = (const float*)d_in[11];
    const float* g1 = (const float*)d_in[12]; const float* be1 = (const float*)d_in[13];
    const float* g2 = (const float*)d_in[14]; const float* be2 = (const float*)d_in[15];
    const float* g3 = (const float*)d_in[16]; const float* be3 = (const float*)d_in[17];
    const float* W1 = (const float*)d_in[18]; const float* b1 = (const float*)d_in[19];
    const float* W2 = (const float*)d_in[20]; const float* b2 = (const float*)d_in[21];
    const float* Wg = (const float*)d_in[22]; const float* bg = (const float*)d_in[23];
    float* out = (float*)d_out;

    float* mem   = sym(g_mem);
    float* kbuf  = sym(g_k);
    float* vbuf  = sym(g_v);
    float* tln   = sym(g_tln);
    float* qbuf  = sym(g_q);
    float* attn  = sym(g_attn);
    float* oproj = sym(g_oproj);
    float* t2    = sym(g_t2);
    float* ff1   = sym(g_ff1);
    float* ff2   = sym(g_ff2);
    float* hbuf  = sym(g_h);

    const int MBN = CB * CN;   // 6272  (= 49 * 128)
    const int MBG = CB * CG;   // 32768

    // 0) tln = LN(2*query), q = tln @ Wq  (batch-independent, input-only deps;
    //    launched first so the fixed ncu profiling slot lands on a big kernel)
    ln_residual_kernel<<<CG, 256>>>(query, query, g1, be1, tln, CG);
    gemm_tf32_kernel<false><<<dim3(CD / BN, CG / BM), 256>>>(
        tln, Wq, bq, qbuf, CG, CD, CD);

    // 1) mem = relu(x @ W_embed + b_embed)
    gemm_tf32_kernel<true><<<dim3(CD / BN, MBN / BM), 256>>>(
        x, W_embed, b_embed, mem, MBN, CD, CIN);

    // 2) k, v projections
    gemm_tf32_kernel<false><<<dim3(CD / BN, MBN / BM), 256>>>(
        mem, Wk, bk, kbuf, MBN, CD, CD);
    gemm_tf32_kernel<false><<<dim3(CD / BN, MBN / BM), 256>>>(
        mem, Wv, bv, vbuf, MBN, CD, CD);

    // 3) attention
    attn_kernel<<<dim3(CH, CB), 256>>>(qbuf, kbuf, vbuf, attn);

    // 4) o-projection
    gemm_tf32_kernel<false><<<dim3(CD / BN, MBG / BM), 256>>>(
        attn, Wo, bo, oproj, MBG, CD, CD);

    // 5) t2 = LN(oproj + tln[g])
    ln_residual_kernel<<<MBG, 256>>>(oproj, tln, g2, be2, t2, CG);

    // 6) ff1 = relu(t2 @ W1 + b1)
    gemm_tf32_kernel<true><<<dim3(CFF / BN, MBG / BM), 256>>>(
        t2, W1, b1, ff1, MBG, CFF, CD);

    // 7) ff2 = ff1 @ W2 + b2
    gemm_tf32_kernel<false><<<dim3(CD / BN, MBG / BM), 256>>>(
        ff1, W2, b2, ff2, MBG, CD, CFF);

    // 8) h = LN(ff2 + t2)
    ln_residual_kernel<<<MBG, 256>>>(ff2, t2, g3, be3, hbuf, MBG);

    // 9) GroupFC -> logits
    groupfc_kernel<<<dim3(CG, CB / 64), 16 * CDUP>>>(hbuf, Wg, bg, out);
}

// round 7
// speedup vs baseline: 1.1128x; 1.1128x over previous
#include <cuda_runtime.h>
#include <math.h>
#include <stdint.h>

// ---------------- problem constants ----------------
#define CB   128     // batch
#define CN   49      // spatial tokens
#define CIN  2048    // backbone channels
#define CG   256     // query groups
#define CD   768     // decoder dim
#define CH   8       // heads
#define CHD  96      // head dim
#define CFF  2048    // ffn dim
#define NCLS 12547
#define CDUP 50

// ---------------- scratch (device globals; no allocation allowed) ----------------
__device__ float g_mem  [CB*CN*CD];
__device__ float g_k    [CB*CN*CD];
__device__ float g_v    [CB*CN*CD];
__device__ float g_tln  [CG*CD];
__device__ float g_q    [CG*CD];
__device__ float g_attn [CB*CG*CD];
__device__ float g_oproj[CB*CG*CD];
__device__ float g_t2   [CB*CG*CD];
__device__ float g_ff1  [CB*CG*CFF];
__device__ float g_ff2  [CB*CG*CD];
__device__ float g_h    [CB*CG*CD];

// ============================================================================
// TF32 tensor-core GEMM: C[M,N] = A[M,K] @ B[K,N] + bias[N]  (optional ReLU)
// Requires M%128==0, N%128==0, K%16==0 (true for all calls here).
// 128x128x16 block tile, 256 threads (8 warps, 4x2), warp tile 32x64.
// Fragment loads via ldmatrix.m8n8.x4.b16:
//   A kept [m][k] (stride 20 floats): 2 LDSM/kk-step (was 8 LDS.32)
//   B stored TRANSPOSED [n][k] (stride 20): 4 LDSM/kk-step (was 16 LDS.32)
// B transpose done at staging: 4 coalesced LDG.32 down k + STS.128 along k
// (start banks 20*lane mod 32 all distinct -> conflict-free).
// cvt.rna.tf32 applied at STS time -> numerics identical to prior rounds.
// ============================================================================
#define BM 128
#define BN 128
#define BK 16
#define ASTRIDE 20           // floats; 80B rows: 16B aligned, LDSM-conflict-free
#define BTS     20           // BsT [n][k] stride, same property
#define ASZ (BM * ASTRIDE)   // 2560 floats
#define BSZ (BN * BTS)       // 2560 floats

__device__ __forceinline__ float to_tf32(float x) {
    asm("cvt.rna.tf32.f32 %0, %0;" : "+f"(x));
    return x;
}

__device__ __forceinline__ void mma1688(float* d, const uint32_t* a, const uint32_t* b) {
    asm volatile(
        "mma.sync.aligned.m16n8k8.row.col.f32.tf32.tf32.f32 "
        "{%0,%1,%2,%3}, {%4,%5,%6,%7}, {%8,%9}, {%0,%1,%2,%3};"
        : "+f"(d[0]), "+f"(d[1]), "+f"(d[2]), "+f"(d[3])
        : "r"(a[0]), "r"(a[1]), "r"(a[2]), "r"(a[3]), "r"(b[0]), "r"(b[1]));
}

__device__ __forceinline__ void ldsm_x4(uint32_t& r0, uint32_t& r1, uint32_t& r2,
                                        uint32_t& r3, uint32_t addr) {
    asm volatile("ldmatrix.sync.aligned.m8n8.x4.shared.b16 {%0,%1,%2,%3}, [%4];"
                 : "=r"(r0), "=r"(r1), "=r"(r2), "=r"(r3) : "r"(addr));
}

template<bool RELU>
__global__ __launch_bounds__(256, 2) void gemm_tf32_kernel(
    const float* __restrict__ A, const float* __restrict__ B,
    const float* __restrict__ bias, float* __restrict__ C,
    int M, int N, int K)
{
    __shared__ float As [2][ASZ];
    __shared__ float BsT[2][BSZ];

    const int tid  = threadIdx.x;
    const int lane = tid & 31;
    const int warp = tid >> 5;
    const int wm   = warp & 3;        // 4 warps along M
    const int wn   = warp >> 2;       // 2 warps along N
    const int m0   = blockIdx.y * BM;
    const int n0   = blockIdx.x * BN;
    const int t    = lane & 3;        // 0..3
    const int g    = lane >> 2;       // 0..7

    // ---- A staging (row-major [m][k], float4 along K) ----
    const int i0 = tid, i1 = tid + 256;
    const int ar0 = i0 >> 2,  ac0 = (i0 & 3) * 4;
    const int ar1 = i1 >> 2,  ac1 = (i1 & 3) * 4;
    const float* Ap0 = A + (size_t)(m0 + ar0) * K + ac0;
    const float* Ap1 = A + (size_t)(m0 + ar1) * K + ac1;

    // ---- B staging (transpose): thread owns column n, k rows {k4..k4+3, k4+8..k4+11} ----
    const int bn  = tid & 127;           // n within tile
    const int bk4 = (tid >> 7) * 4;      // 0 or 4
    const float* Bp = B + n0 + bn;

    float acc[2][8][4];
    #pragma unroll
    for (int im = 0; im < 2; im++)
        #pragma unroll
        for (int in = 0; in < 8; in++)
            #pragma unroll
            for (int r = 0; r < 4; r++) acc[im][in][r] = 0.f;

    const int warp_m = wm * 32;
    const int warp_n = wn * 64;
    const int nT = K / BK;

    // per-lane ldmatrix address components (constant across iters except kk/base)
    const int a_row0 = warp_m + (lane & 15);                 // im adds 16
    const int b_rowc = warp_n + (lane & 7) + ((lane >> 4) & 1) * 8;  // j adds 16
    const int a_koff = (lane >> 4) << 2;                     // 0 or 4
    const int b_koff = ((lane >> 3) & 1) << 2;               // 0 or 4

    // ---- prologue: tile 0 -> regs -> smem[0]; prefetch tile 1 ----
    float4 ra0 = *(const float4*)Ap0;
    float4 ra1 = *(const float4*)Ap1;
    float4 rb0, rb1;
    {
        rb0.x = Bp[(size_t)(bk4 + 0) * N];  rb0.y = Bp[(size_t)(bk4 + 1) * N];
        rb0.z = Bp[(size_t)(bk4 + 2) * N];  rb0.w = Bp[(size_t)(bk4 + 3) * N];
        rb1.x = Bp[(size_t)(bk4 + 8) * N];  rb1.y = Bp[(size_t)(bk4 + 9) * N];
        rb1.z = Bp[(size_t)(bk4 +10) * N];  rb1.w = Bp[(size_t)(bk4 +11) * N];
    }
    {
        float4 v;
        v.x = to_tf32(ra0.x); v.y = to_tf32(ra0.y); v.z = to_tf32(ra0.z); v.w = to_tf32(ra0.w);
        *(float4*)&As[0][ar0 * ASTRIDE + ac0] = v;
        v.x = to_tf32(ra1.x); v.y = to_tf32(ra1.y); v.z = to_tf32(ra1.z); v.w = to_tf32(ra1.w);
        *(float4*)&As[0][ar1 * ASTRIDE + ac1] = v;
        v.x = to_tf32(rb0.x); v.y = to_tf32(rb0.y); v.z = to_tf32(rb0.z); v.w = to_tf32(rb0.w);
        *(float4*)&BsT[0][bn * BTS + bk4] = v;
        v.x = to_tf32(rb1.x); v.y = to_tf32(rb1.y); v.z = to_tf32(rb1.z); v.w = to_tf32(rb1.w);
        *(float4*)&BsT[0][bn * BTS + bk4 + 8] = v;
    }
    if (nT > 1) {
        ra0 = *(const float4*)(Ap0 + BK);
        ra1 = *(const float4*)(Ap1 + BK);
        const float* bp = Bp + (size_t)BK * N;
        rb0.x = bp[(size_t)(bk4 + 0) * N];  rb0.y = bp[(size_t)(bk4 + 1) * N];
        rb0.z = bp[(size_t)(bk4 + 2) * N];  rb0.w = bp[(size_t)(bk4 + 3) * N];
        rb1.x = bp[(size_t)(bk4 + 8) * N];  rb1.y = bp[(size_t)(bk4 + 9) * N];
        rb1.z = bp[(size_t)(bk4 +10) * N];  rb1.w = bp[(size_t)(bk4 +11) * N];
    }
    __syncthreads();

    // ---- mainloop ----
    for (int it = 0; it < nT; ++it) {
        const int cur = it & 1;

        if (it + 1 < nT) {
            float* as = As [cur ^ 1];
            float* bs = BsT[cur ^ 1];
            float4 v;
            v.x = to_tf32(ra0.x); v.y = to_tf32(ra0.y); v.z = to_tf32(ra0.z); v.w = to_tf32(ra0.w);
            *(float4*)&as[ar0 * ASTRIDE + ac0] = v;
            v.x = to_tf32(ra1.x); v.y = to_tf32(ra1.y); v.z = to_tf32(ra1.z); v.w = to_tf32(ra1.w);
            *(float4*)&as[ar1 * ASTRIDE + ac1] = v;
            v.x = to_tf32(rb0.x); v.y = to_tf32(rb0.y); v.z = to_tf32(rb0.z); v.w = to_tf32(rb0.w);
            *(float4*)&bs[bn * BTS + bk4] = v;
            v.x = to_tf32(rb1.x); v.y = to_tf32(rb1.y); v.z = to_tf32(rb1.z); v.w = to_tf32(rb1.w);
            *(float4*)&bs[bn * BTS + bk4 + 8] = v;
        }
        if (it + 2 < nT) {
            const int kp = (it + 2) * BK;
            ra0 = *(const float4*)(Ap0 + kp);
            ra1 = *(const float4*)(Ap1 + kp);
            const float* bp = Bp + (size_t)kp * N;
            rb0.x = bp[(size_t)(bk4 + 0) * N];  rb0.y = bp[(size_t)(bk4 + 1) * N];
            rb0.z = bp[(size_t)(bk4 + 2) * N];  rb0.w = bp[(size_t)(bk4 + 3) * N];
            rb1.x = bp[(size_t)(bk4 + 8) * N];  rb1.y = bp[(size_t)(bk4 + 9) * N];
            rb1.z = bp[(size_t)(bk4 +10) * N];  rb1.w = bp[(size_t)(bk4 +11) * N];
        }

        const uint32_t as_u = (uint32_t)__cvta_generic_to_shared(As [cur]);
        const uint32_t bs_u = (uint32_t)__cvta_generic_to_shared(BsT[cur]);

        #pragma unroll
        for (int kk = 0; kk < BK; kk += 8) {
            uint32_t af[2][4];
            #pragma unroll
            for (int im = 0; im < 2; im++) {
                uint32_t addr = as_u + ((a_row0 + im * 16) * ASTRIDE + kk + a_koff) * 4;
                ldsm_x4(af[im][0], af[im][1], af[im][2], af[im][3], addr);
            }
            uint32_t bf[8][2];
            #pragma unroll
            for (int j = 0; j < 4; j++) {
                uint32_t addr = bs_u + ((b_rowc + j * 16) * BTS + kk + b_koff) * 4;
                ldsm_x4(bf[2*j][0], bf[2*j][1], bf[2*j+1][0], bf[2*j+1][1], addr);
            }
            #pragma unroll
            for (int im = 0; im < 2; im++)
                #pragma unroll
                for (int in = 0; in < 8; in++)
                    mma1688(acc[im][in], af[im], bf[in]);
        }
        __syncthreads();
    }

    // ---- epilogue: bias (+ReLU), direct to gmem ----
    #pragma unroll
    for (int in = 0; in < 8; in++) {
        const int c0 = n0 + warp_n + in * 8 + t * 2;
        float2 bv = *(const float2*)(bias + c0);
        #pragma unroll
        for (int im = 0; im < 2; im++) {
            const int r0 = m0 + warp_m + im * 16 + g;
            float2 o0, o1;
            o0.x = acc[im][in][0] + bv.x;
            o0.y = acc[im][in][1] + bv.y;
            o1.x = acc[im][in][2] + bv.x;
            o1.y = acc[im][in][3] + bv.y;
            if (RELU) {
                o0.x = fmaxf(o0.x, 0.f); o0.y = fmaxf(o0.y, 0.f);
                o1.x = fmaxf(o1.x, 0.f); o1.y = fmaxf(o1.y, 0.f);
            }
            *(float2*)(C + (size_t)r0 * N + c0)       = o0;
            *(float2*)(C + (size_t)(r0 + 8) * N + c0) = o1;
        }
    }
}

// ============================================================================
// LayerNorm over D=768 with fused residual: out[row] = LN(a[row] + res[row % rowmod])
// ============================================================================
__global__ __launch_bounds__(256) void ln_residual_kernel(
    const float* __restrict__ a, const float* __restrict__ res,
    const float* __restrict__ gamma, const float* __restrict__ beta,
    float* __restrict__ out, int rowmod)
{
    __shared__ float sh[8];
    __shared__ float s_mean, s_rstd;

    const int row = blockIdx.x;
    const int tid = threadIdx.x;
    const float* ar = a   + (size_t)row * CD;
    const float* rr = res + (size_t)(row % rowmod) * CD;

    float x[3];
    #pragma unroll
    for (int i = 0; i < 3; i++) {
        int j = tid + i * 256;
        x[i] = ar[j] + rr[j];
    }

    float s = x[0] + x[1] + x[2];
    #pragma unroll
    for (int o = 16; o > 0; o >>= 1) s += __shfl_down_sync(0xffffffffu, s, o);
    if ((tid & 31) == 0) sh[tid >> 5] = s;
    __syncthreads();
    if (tid < 32) {
        float v = (tid < 8) ? sh[tid] : 0.f;
        #pragma unroll
        for (int o = 4; o > 0; o >>= 1) v += __shfl_down_sync(0xffffffffu, v, o);
        if (tid == 0) s_mean = v * (1.f / CD);
    }
    __syncthreads();
    const float m = s_mean;

    float d2 = 0.f;
    #pragma unroll
    for (int i = 0; i < 3; i++) { float d = x[i] - m; d2 += d * d; }
    #pragma unroll
    for (int o = 16; o > 0; o >>= 1) d2 += __shfl_down_sync(0xffffffffu, d2, o);
    if ((tid & 31) == 0) sh[tid >> 5] = d2;
    __syncthreads();
    if (tid < 32) {
        float v = (tid < 8) ? sh[tid] : 0.f;
        #pragma unroll
        for (int o = 4; o > 0; o >>= 1) v += __shfl_down_sync(0xffffffffu, v, o);
        if (tid == 0) s_rstd = rsqrtf(v * (1.f / CD) + 1e-5f);
    }
    __syncthreads();
    const float rs = s_rstd;

    float* orow = out + (size_t)row * CD;
    #pragma unroll
    for (int i = 0; i < 3; i++) {
        int j = tid + i * 256;
        orow[j] = (x[i] - m) * rs * gamma[j] + beta[j];
    }
}

// ============================================================================
// Cross-attention. q is batch-independent [G, D]. k,v: [B, N, D]. o: [B, G, D].
// ============================================================================
__global__ __launch_bounds__(256) void attn_kernel(
    const float* __restrict__ q, const float* __restrict__ k,
    const float* __restrict__ v, float* __restrict__ o)
{
    const int h = blockIdx.x;
    const int b = blockIdx.y;
    __shared__ float ks[CN][CHD];
    __shared__ float vs[CN][CHD];

    const int tid = threadIdx.x;
    for (int i = tid; i < CN * CHD; i += 256) {
        int n = i / CHD, d = i % CHD;
        size_t gi = (size_t)(b * CN + n) * CD + h * CHD + d;
        ks[n][d] = k[gi];
        vs[n][d] = v[gi];
    }
    __syncthreads();

    const int g = tid;
    float p[CN];
    #pragma unroll
    for (int n = 0; n < CN; n++) p[n] = 0.f;

    const float* qrow = q + (size_t)g * CD + h * CHD;
    for (int dc = 0; dc < CHD; dc += 8) {
        float q8[8];
        #pragma unroll
        for (int j = 0; j < 8; j++) q8[j] = qrow[dc + j];
        #pragma unroll
        for (int n = 0; n < CN; n++) {
            float s = 0.f;
            #pragma unroll
            for (int j = 0; j < 8; j++) s += q8[j] * ks[n][dc + j];
            p[n] += s;
        }
    }

    const float scale = rsqrtf((float)CHD);
    float mx = -1e30f;
    #pragma unroll
    for (int n = 0; n < CN; n++) { p[n] *= scale; mx = fmaxf(mx, p[n]); }
    float sum = 0.f;
    #pragma unroll
    for (int n = 0; n < CN; n++) { p[n] = expf(p[n] - mx); sum += p[n]; }
    const float inv = 1.f / sum;
    #pragma unroll
    for (int n = 0; n < CN; n++) p[n] *= inv;

    float* orow = o + (size_t)(b * CG + g) * CD + h * CHD;
    for (int d = 0; d < CHD; d++) {
        float acc = 0.f;
        #pragma unroll
        for (int n = 0; n < CN; n++) acc += p[n] * vs[n][d];
        orow[d] = acc;
    }
}

// ============================================================================
// GroupFC: logits[b, g*50+f] = h[b,g,:] . Wg[g,:,f] + bg
// 4-batch register blocking (Wg re-read cut 4x).
// ============================================================================
__global__ __launch_bounds__(800) void groupfc_kernel(
    const float* __restrict__ h, const float* __restrict__ Wg,
    const float* __restrict__ bg, float* __restrict__ out)
{
    const int g   = blockIdx.x;
    const int tid = threadIdx.x;
    const int f   = tid % CDUP;
    const int bi  = tid / CDUP;            // 0..15
    const int b0  = blockIdx.y * 64 + bi;  // + {0,16,32,48}

    const float* w  = Wg + (size_t)g * CD * CDUP + f;
    const float* h0 = h + ((size_t)(b0     ) * CG + g) * CD;
    const float* h1 = h + ((size_t)(b0 + 16) * CG + g) * CD;
    const float* h2 = h + ((size_t)(b0 + 32) * CG + g) * CD;
    const float* h3 = h + ((size_t)(b0 + 48) * CG + g) * CD;

    float a0 = 0.f, a1 = 0.f, a2 = 0.f, a3 = 0.f;
    #pragma unroll 4
    for (int d = 0; d < CD; d++) {
        float wv = w[(size_t)d * CDUP];
        a0 += h0[d] * wv;
        a1 += h1[d] * wv;
        a2 += h2[d] * wv;
        a3 += h3[d] * wv;
    }

    const int c = g * CDUP + f;
    if (c < NCLS) {
        const float bb = bg[c];
        out[(size_t)(b0     ) * NCLS + c] = a0 + bb;
        out[(size_t)(b0 + 16) * NCLS + c] = a1 + bb;
        out[(size_t)(b0 + 32) * NCLS + c] = a2 + bb;
        out[(size_t)(b0 + 48) * NCLS + c] = a3 + bb;
    }
}

// ============================================================================
// Orchestration
// ============================================================================
static inline float* sym(const void* s)
{
    void* p = nullptr;
    cudaGetSymbolAddress(&p, s);
    return (float*)p;
}

extern "C" void kernel_launch(void* const* d_in, const int* in_sizes, int n_in,
                              void* d_out, int out_size)
{
    const float* x       = (const float*)d_in[0];
    const float* W_embed = (const float*)d_in[1];
    const float* b_embed = (const float*)d_in[2];
    const float* query   = (const float*)d_in[3];
    const float* Wq = (const float*)d_in[4];  const float* bq = (const float*)d_in[5];
    const float* Wk = (const float*)d_in[6];  const float* bk = (const float*)d_in[7];
    const float* Wv = (const float*)d_in[8];  const float* bv = (const float*)d_in[9];
    const float* Wo = (const float*)d_in[10]; const float* bo = (const float*)d_in[11];
    const float* g1 = (const float*)d_in[12]; const float* be1 = (const float*)d_in[13];
    const float* g2 = (const float*)d_in[14]; const float* be2 = (const float*)d_in[15];
    const float* g3 = (const float*)d_in[16]; const float* be3 = (const float*)d_in[17];
    const float* W1 = (const float*)d_in[18]; const float* b1 = (const float*)d_in[19];
    const float* W2 = (const float*)d_in[20]; const float* b2 = (const float*)d_in[21];
    const float* Wg = (const float*)d_in[22]; const float* bg = (const float*)d_in[23];
    float* out = (float*)d_out;

    float* mem   = sym(g_mem);
    float* kbuf  = sym(g_k);
    float* vbuf  = sym(g_v);
    float* tln   = sym(g_tln);
    float* qbuf  = sym(g_q);
    float* attn  = sym(g_attn);
    float* oproj = sym(g_oproj);
    float* t2    = sym(g_t2);
    float* ff1   = sym(g_ff1);
    float* ff2   = sym(g_ff2);
    float* hbuf  = sym(g_h);

    const int MBN = CB * CN;   // 6272  (= 49 * 128)
    const int MBG = CB * CG;   // 32768

    // 0) batch-independent: tln = LN(2*query); q = tln @ Wq
    ln_residual_kernel<<<CG, 256>>>(query, query, g1, be1, tln, CG);
    gemm_tf32_kernel<false><<<dim3(CD / BN, CG / BM), 256>>>(
        tln, Wq, bq, qbuf, CG, CD, CD);

    // 1) mem = relu(x @ W_embed + b_embed)
    gemm_tf32_kernel<true><<<dim3(CD / BN, MBN / BM), 256>>>(
        x, W_embed, b_embed, mem, MBN, CD, CIN);

    // 2) k, v projections
    gemm_tf32_kernel<false><<<dim3(CD / BN, MBN / BM), 256>>>(
        mem, Wk, bk, kbuf, MBN, CD, CD);
    gemm_tf32_kernel<false><<<dim3(CD / BN, MBN / BM), 256>>>(
        mem, Wv, bv, vbuf, MBN, CD, CD);

    // 3) attention
    attn_kernel<<<dim3(CH, CB), 256>>>(qbuf, kbuf, vbuf, attn);

    // 4) o-projection
    gemm_tf32_kernel<false><<<dim3(CD / BN, MBG / BM), 256>>>(
        attn, Wo, bo, oproj, MBG, CD, CD);

    // 5) t2 = LN(oproj + tln[g])
    ln_residual_kernel<<<MBG, 256>>>(oproj, tln, g2, be2, t2, CG);

    // 6) ff1 = relu(t2 @ W1 + b1)
    gemm_tf32_kernel<true><<<dim3(CFF / BN, MBG / BM), 256>>>(
        t2, W1, b1, ff1, MBG, CFF, CD);

    // 7) ff2 = ff1 @ W2 + b2
    gemm_tf32_kernel<false><<<dim3(CD / BN, MBG / BM), 256>>>(
        ff1, W2, b2, ff2, MBG, CD, CFF);

    // 8) h = LN(ff2 + t2)
    ln_residual_kernel<<<MBG, 256>>>(ff2, t2, g3, be3, hbuf, MBG);

    // 9) GroupFC -> logits
    groupfc_kernel<<<dim3(CG, CB / 64), 16 * CDUP>>>(hbuf, Wg, bg, out);
}